// round 2
// baseline (speedup 1.0000x reference)
#include <cuda_runtime.h>
#include <math.h>

#define NN 2048          // nodes
#define MM 512           // groups
#define DD 32            // per-manifold dim
#define NSEG 8           // k-segments for CSC build
#define SEGLEN 256       // NN / NSEG
#define CAP 256          // member cache capacity in k_agg1
#define FULL 0xffffffffu

// ---------------- device scratch (no allocs allowed) ----------------
__device__ float g_xh[NN*DD], g_xs[NN*DD], g_xe[NN*DD];
__device__ float g_lamx[NN*DD];
__device__ float g_lamm1[NN];
__device__ float g_xsn2[NN];

__device__ int   g_csr[NN*MM];       // per-row member cols (cap 512)
__device__ int   g_csr_cnt[NN];
__device__ int   g_csc[MM*NN];       // per-col slab: 8 segments x 256
__device__ int   g_csc_cnt[MM*NSEG];

__device__ float g_eh[MM*DD], g_es[MM*DD], g_ee[MM*DD];
__device__ float g_elamx[MM*DD];
__device__ float g_elamm1[MM];
__device__ float g_esn2[MM];

// ---------------- helpers ----------------
__device__ __forceinline__ float wsum(float v) {
    #pragma unroll
    for (int o = 16; o; o >>= 1) v += __shfl_xor_sync(FULL, v, o);
    return v;
}
__device__ __forceinline__ float clip1(float v) {
    return fminf(fmaxf(v, -1.0f + 1e-6f), 1.0f - 1e-6f);
}

// ---------------- CSR build: warp per row, ballot-compaction ----------------
__global__ void k_build_csr(const float* __restrict__ H) {
    int warp = (blockIdx.x * blockDim.x + threadIdx.x) >> 5;
    int lane = threadIdx.x & 31;
    if (warp >= NN) return;
    const float* row = H + (size_t)warp * MM;
    int cnt = 0;
    for (int gb = 0; gb < MM; gb += 32) {
        float h = row[gb + lane];
        unsigned mask = __ballot_sync(FULL, h > 0.5f);
        if (lane == 0) {
            while (mask) {
                int b = __ffs(mask) - 1;
                g_csr[warp * MM + cnt++] = gb + b;
                mask &= mask - 1;
            }
        }
    }
    if (lane == 0) g_csr_cnt[warp] = cnt;
}

// ---------------- CSC build: 8 blocks x 512 threads (thread = column) ------
__global__ void k_build_csc(const float* __restrict__ H) {
    int g = threadIdx.x;
    int b = blockIdx.x;
    int cnt = 0;
    int base = g * NN + b * SEGLEN;
    int k0 = b * SEGLEN;
    for (int j = 0; j < SEGLEN; j++) {
        float h = H[(size_t)(k0 + j) * MM + g];   // coalesced across g
        if (h > 0.5f) g_csc[base + cnt++] = k0 + j;
    }
    g_csc_cnt[g * NSEG + b] = cnt;
}

// ---------------- per-node feature transform (warp per node) ----------------
__global__ void k_transform(const float* __restrict__ x,
                            const float* __restrict__ Wh, const float* __restrict__ bh,
                            const float* __restrict__ Ws, const float* __restrict__ bs,
                            const float* __restrict__ We, const float* __restrict__ be,
                            const float* __restrict__ cph) {
    __shared__ float sW[3 * DD * DD];
    __shared__ float sB[3 * DD];
    for (int i = threadIdx.x; i < DD * DD; i += blockDim.x) {
        sW[i]             = Wh[i];
        sW[DD*DD + i]     = Ws[i];
        sW[2*DD*DD + i]   = We[i];
    }
    if (threadIdx.x < DD) {
        sB[threadIdx.x]        = bh[threadIdx.x];
        sB[DD + threadIdx.x]   = bs[threadIdx.x];
        sB[2*DD + threadIdx.x] = be[threadIdx.x];
    }
    __syncthreads();

    int r    = blockIdx.x * (blockDim.x >> 5) + (threadIdx.x >> 5);
    int lane = threadIdx.x & 31;
    if (r >= NN) return;

    float c  = fabsf(*cph) + 1e-6f;
    float sc = sqrtf(c);
    float maxn = (1.0f - 1e-5f) / sc;

    float xh = x[r * 96 + lane];
    float xs = x[r * 96 + 32 + lane];
    float xe = x[r * 96 + 64 + lane];

    // hyp_project(x_h)
    float n  = sqrtf(wsum(xh * xh));
    float nm = fmaxf(n, 1e-6f);
    if (nm > maxn) xh *= maxn / nm;

    // logmap0
    n = fmaxf(sqrtf(wsum(xh * xh)), 1e-6f);
    float arg = clip1(sc * n);
    float lg  = atanhf(arg) * xh / (sc * n);

    // v = lg @ Wh^T + bh
    float v = sB[lane];
    #pragma unroll
    for (int i = 0; i < DD; i++)
        v = fmaf(__shfl_sync(FULL, lg, i), sW[lane * DD + i], v);

    // expmap0
    n = fmaxf(sqrtf(wsum(v * v)), 1e-6f);
    float xh2 = tanhf(sc * n) * v / (sc * n);
    // hyp_project
    n  = sqrtf(wsum(xh2 * xh2));
    nm = fmaxf(n, 1e-6f);
    if (nm > maxn) xh2 *= maxn / nm;

    float sq  = wsum(xh2 * xh2);
    float lam = 2.0f / fmaxf(1.0f - c * sq, 1e-6f);
    g_xh[r * DD + lane]   = xh2;
    g_lamx[r * DD + lane] = lam * xh2;
    if (lane == 0) g_lamm1[r] = lam - 1.0f;

    // sphere branch
    n = fmaxf(sqrtf(wsum(xs * xs)), 1e-6f);
    xs /= n;
    float s2 = sB[DD + lane];
    #pragma unroll
    for (int i = 0; i < DD; i++)
        s2 = fmaf(__shfl_sync(FULL, xs, i), sW[DD*DD + lane * DD + i], s2);
    n = fmaxf(sqrtf(wsum(s2 * s2)), 1e-6f);
    s2 /= n;
    g_xs[r * DD + lane] = s2;
    float pn = wsum(s2 * s2);
    if (lane == 0) g_xsn2[r] = pn;

    // euclidean branch
    float e2 = sB[2*DD + lane];
    #pragma unroll
    for (int i = 0; i < DD; i++)
        e2 = fmaf(__shfl_sync(FULL, xe, i), sW[2*DD*DD + lane * DD + i], e2);
    g_xe[r * DD + lane] = e2;
}

// ---------------- stage 1: nodes -> 512 groups (block per group) ----------------
// Phase A compacts member list + caches point vectors in SMEM; phase B (5 Frechet
// iterations) then runs fully out of shared memory (global fallback if cnt > CAP).
__global__ void k_agg1(const float* __restrict__ cph) {
    __shared__ float s_p[CAP * DD];     // cached sphere points (32 KB)
    __shared__ float s_pp[CAP];         // cached squared norms
    __shared__ float s_mu[DD];
    __shared__ float s_vec[4][3][DD];
    __shared__ float s_sc[4];
    __shared__ int   s_off[NSEG];
    __shared__ int   s_tot;

    int g    = blockIdx.x;
    int w    = threadIdx.x >> 5;
    int lane = threadIdx.x & 31;

    float c  = fabsf(*cph) + 1e-6f;
    float sc = sqrtf(c);

    if (threadIdx.x == 0) {
        int acc = 0;
        for (int s = 0; s < NSEG; s++) { s_off[s] = acc; acc += g_csc_cnt[g * NSEG + s]; }
        s_tot = acc;
    }
    __syncthreads();
    int tot = s_tot;
    bool cache = (tot <= CAP);
    float cntf = (float)tot;

    // ---- phase A: linear sums + SMEM member cache ----
    float sp = 0.f, sl = 0.f, se = 0.f, sm = 0.f;
    for (int seg = w; seg < NSEG; seg += 4) {
        int cnt = g_csc_cnt[g * NSEG + seg];
        const int* lst = g_csc + g * NN + seg * SEGLEN;
        int off = s_off[seg];
        for (int j = 0; j < cnt; j++) {
            int k = lst[j];
            float p = g_xs[k * DD + lane];
            sp += p;
            sl += g_lamx[k * DD + lane];
            se += g_xe[k * DD + lane];
            sm += g_lamm1[k];
            if (cache) {
                s_p[(off + j) * DD + lane] = p;
                if (lane == 0) s_pp[off + j] = g_xsn2[k];
            }
        }
    }
    s_vec[w][0][lane] = sp;
    s_vec[w][1][lane] = sl;
    s_vec[w][2][lane] = se;
    if (lane == 0) s_sc[w] = sm;
    __syncthreads();

    if (w == 0) {
        float tp = 0.f, tl = 0.f, te = 0.f, tm = 0.f;
        #pragma unroll
        for (int u = 0; u < 4; u++) {
            tp += s_vec[u][0][lane];
            tl += s_vec[u][1][lane];
            te += s_vec[u][2][lane];
            tm += s_sc[u];
        }
        g_ee[g * DD + lane] = te / fmaxf(cntf, 1e-6f);

        // gyromidpoint
        float den = fmaxf(tm, 1e-6f);
        float y   = tl / den;
        float yn  = fmaxf(sqrtf(wsum(y * y)), 1e-6f);
        float arg = clip1(sc * yn);
        float eh  = tanhf(0.5f * atanhf(arg)) * y / (sc * yn);
        g_eh[g * DD + lane] = eh;
        float sq  = wsum(eh * eh);
        float lam = 2.0f / fmaxf(1.0f - c * sq, 1e-6f);
        g_elamx[g * DD + lane] = lam * eh;
        if (lane == 0) g_elamm1[g] = lam - 1.0f;

        // sphere mu0
        float mu = tp / cntf;
        mu /= fmaxf(sqrtf(wsum(mu * mu)), 1e-6f);
        s_mu[lane] = mu;
    }
    __syncthreads();

    // ---- phase B: 5 Frechet iterations (SMEM-resident) ----
    for (int it = 0; it < 5; it++) {
        float mu = s_mu[lane];
        float mm = wsum(mu * mu);
        float t = 0.f, bsum = 0.f;
        if (cache) {
            for (int m = w; m < tot; m += 4) {
                float p    = s_p[m * DD + lane];
                float pp   = s_pp[m];
                float draw = wsum(mu * p);
                float dotc = clip1(draw);
                float theta = acosf(dotc);
                float dn2 = pp - dotc * (2.0f * draw - dotc * mm);
                float dn  = fmaxf(sqrtf(fmaxf(dn2, 0.f)), 1e-6f);
                float a   = theta / dn;
                t    = fmaf(a, p, t);
                bsum = fmaf(-a, dotc, bsum);
            }
        } else {
            for (int seg = w; seg < NSEG; seg += 4) {
                int cnt = g_csc_cnt[g * NSEG + seg];
                const int* lst = g_csc + g * NN + seg * SEGLEN;
                for (int j = 0; j < cnt; j++) {
                    int k = lst[j];
                    float p    = g_xs[k * DD + lane];
                    float pp   = g_xsn2[k];
                    float draw = wsum(mu * p);
                    float dotc = clip1(draw);
                    float theta = acosf(dotc);
                    float dn2 = pp - dotc * (2.0f * draw - dotc * mm);
                    float dn  = fmaxf(sqrtf(fmaxf(dn2, 0.f)), 1e-6f);
                    float a   = theta / dn;
                    t    = fmaf(a, p, t);
                    bsum = fmaf(-a, dotc, bsum);
                }
            }
        }
        t = fmaf(bsum, mu, t);
        s_vec[w][0][lane] = t;
        __syncthreads();
        if (w == 0) {
            float avg = 0.f;
            #pragma unroll
            for (int u = 0; u < 4; u++) avg += s_vec[u][0][lane];
            avg /= cntf;
            float vn  = sqrtf(wsum(avg * avg));
            float vns = fmaxf(vn, 1e-6f);
            float res = cosf(vn) * s_mu[lane] + sinf(vn) * avg / vns;
            res /= fmaxf(sqrtf(wsum(res * res)), 1e-6f);
            s_mu[lane] = res;
        }
        __syncthreads();
    }
    if (w == 0) {
        float mu = s_mu[lane];
        g_es[g * DD + lane] = mu;
        float pn = wsum(mu * mu);
        if (lane == 0) g_esn2[g] = pn;
    }
}

// ---------------- stage 2: groups -> 2048 nodes (warp per row) ----------------
__global__ void k_agg2(float* __restrict__ out, const float* __restrict__ cph) {
    int i    = blockIdx.x * (blockDim.x >> 5) + (threadIdx.x >> 5);
    int lane = threadIdx.x & 31;
    if (i >= NN) return;

    float c  = fabsf(*cph) + 1e-6f;
    float sc = sqrtf(c);
    float maxn = (1.0f - 1e-5f) / sc;

    int cnt = g_csr_cnt[i];
    const int* lst = g_csr + i * MM;

    float sp = 0.f, sl = 0.f, se = 0.f, sm = 0.f;
    for (int j = 0; j < cnt; j++) {
        int g = lst[j];
        sp += g_es[g * DD + lane];
        sl += g_elamx[g * DD + lane];
        se += g_ee[g * DD + lane];
        sm += g_elamm1[g];
    }
    float cntf = (float)cnt;

    float oe = se / fmaxf(cntf, 1e-6f);

    // gyromidpoint + final hyp_project
    float den = fmaxf(sm, 1e-6f);
    float y   = sl / den;
    float yn  = fmaxf(sqrtf(wsum(y * y)), 1e-6f);
    float arg = clip1(sc * yn);
    float oh  = tanhf(0.5f * atanhf(arg)) * y / (sc * yn);
    float n   = sqrtf(wsum(oh * oh));
    float nm  = fmaxf(n, 1e-6f);
    if (nm > maxn) oh *= maxn / nm;

    // sphere midpoint
    float mu = sp / cntf;
    mu /= fmaxf(sqrtf(wsum(mu * mu)), 1e-6f);
    for (int it = 0; it < 5; it++) {
        float mm = wsum(mu * mu);
        float t = 0.f, bsum = 0.f;
        for (int j = 0; j < cnt; j++) {
            int g = lst[j];
            float p    = g_es[g * DD + lane];
            float pp   = g_esn2[g];
            float draw = wsum(mu * p);
            float dotc = clip1(draw);
            float theta = acosf(dotc);
            float dn2 = pp - dotc * (2.0f * draw - dotc * mm);
            float dn  = fmaxf(sqrtf(fmaxf(dn2, 0.f)), 1e-6f);
            float a   = theta / dn;
            t    = fmaf(a, p, t);
            bsum = fmaf(-a, dotc, bsum);
        }
        t = fmaf(bsum, mu, t);
        t /= cntf;
        float vn  = sqrtf(wsum(t * t));
        float vns = fmaxf(vn, 1e-6f);
        mu = cosf(vn) * mu + sinf(vn) * t / vns;
        mu /= fmaxf(sqrtf(wsum(mu * mu)), 1e-6f);
    }
    float os = mu / fmaxf(sqrtf(wsum(mu * mu)), 1e-6f);

    out[i * 96 + lane]      = oh;
    out[i * 96 + 32 + lane] = os;
    out[i * 96 + 64 + lane] = oe;
}

// ---------------- launch ----------------
extern "C" void kernel_launch(void* const* d_in, const int* in_sizes, int n_in,
                              void* d_out, int out_size) {
    const float* x   = (const float*)d_in[0];
    const float* H   = (const float*)d_in[1];
    const float* Wh  = (const float*)d_in[2];
    const float* bh  = (const float*)d_in[3];
    const float* Ws  = (const float*)d_in[4];
    const float* bs  = (const float*)d_in[5];
    const float* We  = (const float*)d_in[6];
    const float* be  = (const float*)d_in[7];
    const float* c_h = (const float*)d_in[8];
    float* out = (float*)d_out;

    k_build_csr<<<NN / 8, 256>>>(H);                 // 2048 warps
    k_build_csc<<<NSEG, MM>>>(H);
    k_transform<<<NN / 4, 128>>>(x, Wh, bh, Ws, bs, We, be, c_h);
    k_agg1<<<MM, 128>>>(c_h);
    k_agg2<<<NN / 4, 128>>>(out, c_h);
}

// round 3
// speedup vs baseline: 1.6544x; 1.6544x over previous
#include <cuda_runtime.h>
#include <math.h>

#define NN 2048          // nodes
#define MM 512           // groups
#define DD 32            // per-manifold dim
#define NSEG 32          // k-segments for CSC build
#define SEGLEN 64        // NN / NSEG
#define CAP 256          // member cache capacity in k_agg1
#define PT 257           // padded stride for transposed cache
#define BK 256           // k_agg1 block size (8 warps)
#define FULL 0xffffffffu

// ---------------- device scratch (no allocs allowed) ----------------
__device__ float g_xs[NN*DD], g_xe[NN*DD];
__device__ float g_lamx[NN*DD];
__device__ float g_lamm1[NN];
__device__ float g_xsn2[NN];

__device__ int   g_csr[NN*MM];       // per-row member cols
__device__ int   g_csr_cnt[NN];
__device__ int   g_csc[MM*NN];       // per-col slab: NSEG segments x SEGLEN
__device__ int   g_csc_cnt[MM*NSEG];

__device__ float g_es[MM*DD], g_ee[MM*DD];
__device__ float g_elamx[MM*DD];
__device__ float g_elamm1[MM];
__device__ float g_esn2[MM];

// ---------------- helpers ----------------
__device__ __forceinline__ float wsum(float v) {
    #pragma unroll
    for (int o = 16; o; o >>= 1) v += __shfl_xor_sync(FULL, v, o);
    return v;
}
__device__ __forceinline__ float clip1(float v) {
    return fminf(fmaxf(v, -1.0f + 1e-6f), 1.0f - 1e-6f);
}

// ---------------- CSR build: warp per row, ballot-compaction ----------------
__global__ void k_build_csr(const float* __restrict__ H) {
    int warp = (blockIdx.x * blockDim.x + threadIdx.x) >> 5;
    int lane = threadIdx.x & 31;
    if (warp >= NN) return;
    const float* row = H + (size_t)warp * MM;
    int cnt = 0;
    for (int gb = 0; gb < MM; gb += 32) {
        float h = row[gb + lane];
        unsigned mask = __ballot_sync(FULL, h > 0.5f);
        if (lane == 0) {
            while (mask) {
                int b = __ffs(mask) - 1;
                g_csr[warp * MM + cnt++] = gb + b;
                mask &= mask - 1;
            }
        }
    }
    if (lane == 0) g_csr_cnt[warp] = cnt;
}

// ---------------- CSC build: NSEG blocks x 512 threads (thread = column) ------
__global__ void k_build_csc(const float* __restrict__ H) {
    int g = threadIdx.x;
    int b = blockIdx.x;
    int cnt = 0;
    int base = g * NN + b * SEGLEN;
    int k0 = b * SEGLEN;
    for (int j = 0; j < SEGLEN; j++) {
        float h = H[(size_t)(k0 + j) * MM + g];   // coalesced across g
        if (h > 0.5f) g_csc[base + cnt++] = k0 + j;
    }
    g_csc_cnt[g * NSEG + b] = cnt;
}

// ---------------- per-node feature transform (warp per node) ----------------
__global__ void k_transform(const float* __restrict__ x,
                            const float* __restrict__ Wh, const float* __restrict__ bh,
                            const float* __restrict__ Ws, const float* __restrict__ bs,
                            const float* __restrict__ We, const float* __restrict__ be,
                            const float* __restrict__ cph) {
    __shared__ float sW[3 * DD * DD];
    __shared__ float sB[3 * DD];
    for (int i = threadIdx.x; i < DD * DD; i += blockDim.x) {
        sW[i]             = Wh[i];
        sW[DD*DD + i]     = Ws[i];
        sW[2*DD*DD + i]   = We[i];
    }
    if (threadIdx.x < DD) {
        sB[threadIdx.x]        = bh[threadIdx.x];
        sB[DD + threadIdx.x]   = bs[threadIdx.x];
        sB[2*DD + threadIdx.x] = be[threadIdx.x];
    }
    __syncthreads();

    int r    = blockIdx.x * (blockDim.x >> 5) + (threadIdx.x >> 5);
    int lane = threadIdx.x & 31;
    if (r >= NN) return;

    float c  = fabsf(*cph) + 1e-6f;
    float sc = sqrtf(c);
    float maxn = (1.0f - 1e-5f) / sc;

    float xh = x[r * 96 + lane];
    float xs = x[r * 96 + 32 + lane];
    float xe = x[r * 96 + 64 + lane];

    // hyp_project(x_h)
    float n  = sqrtf(wsum(xh * xh));
    float nm = fmaxf(n, 1e-6f);
    if (nm > maxn) xh *= maxn / nm;

    // logmap0
    n = fmaxf(sqrtf(wsum(xh * xh)), 1e-6f);
    float arg = clip1(sc * n);
    float lg  = atanhf(arg) * xh / (sc * n);

    // v = lg @ Wh^T + bh
    float v = sB[lane];
    #pragma unroll
    for (int i = 0; i < DD; i++)
        v = fmaf(__shfl_sync(FULL, lg, i), sW[lane * DD + i], v);

    // expmap0
    n = fmaxf(sqrtf(wsum(v * v)), 1e-6f);
    float xh2 = tanhf(sc * n) * v / (sc * n);
    // hyp_project
    n  = sqrtf(wsum(xh2 * xh2));
    nm = fmaxf(n, 1e-6f);
    if (nm > maxn) xh2 *= maxn / nm;

    float sq  = wsum(xh2 * xh2);
    float lam = 2.0f / fmaxf(1.0f - c * sq, 1e-6f);
    g_lamx[r * DD + lane] = lam * xh2;
    if (lane == 0) g_lamm1[r] = lam - 1.0f;

    // sphere branch
    n = fmaxf(sqrtf(wsum(xs * xs)), 1e-6f);
    xs /= n;
    float s2 = sB[DD + lane];
    #pragma unroll
    for (int i = 0; i < DD; i++)
        s2 = fmaf(__shfl_sync(FULL, xs, i), sW[DD*DD + lane * DD + i], s2);
    n = fmaxf(sqrtf(wsum(s2 * s2)), 1e-6f);
    s2 /= n;
    g_xs[r * DD + lane] = s2;
    float pn = wsum(s2 * s2);
    if (lane == 0) g_xsn2[r] = pn;

    // euclidean branch
    float e2 = sB[2*DD + lane];
    #pragma unroll
    for (int i = 0; i < DD; i++)
        e2 = fmaf(__shfl_sync(FULL, xe, i), sW[2*DD*DD + lane * DD + i], e2);
    g_xe[r * DD + lane] = e2;
}

// ---------------- stage 1: nodes -> 512 groups (block per group) ----------------
// Phase A compacts members + caches points TRANSPOSED in SMEM. Each Frechet
// iteration then does: (1) member-per-thread dots (no shuffles), (2) dim-per-lane
// weighted accumulation, (3) tiny warp-0 epilogue.
__global__ __launch_bounds__(BK) void k_agg1(const float* __restrict__ cph) {
    __shared__ float s_pT[DD * PT];     // transposed points: [d][m], stride 257
    __shared__ float s_pp[CAP];
    __shared__ float s_a[CAP];
    __shared__ float s_ad[CAP];
    __shared__ float s_mu[DD];
    __shared__ float s_mm;
    __shared__ float s_vec[8][3][DD];
    __shared__ float s_sc[8];
    __shared__ float s_tw[8][DD];
    __shared__ float s_bw[8];
    __shared__ int   s_off[NSEG];
    __shared__ int   s_tot;

    int g    = blockIdx.x;
    int w    = threadIdx.x >> 5;
    int lane = threadIdx.x & 31;
    int tid  = threadIdx.x;

    float c  = fabsf(*cph) + 1e-6f;
    float sc = sqrtf(c);

    if (tid == 0) {
        int acc = 0;
        for (int s = 0; s < NSEG; s++) { s_off[s] = acc; acc += g_csc_cnt[g * NSEG + s]; }
        s_tot = acc;
    }
    __syncthreads();
    int tot = s_tot;
    bool cache = (tot <= CAP);
    float cntf = (float)tot;

    // ---- phase A: linear sums + transposed SMEM member cache ----
    float sp = 0.f, sl = 0.f, se = 0.f, sm = 0.f;
    for (int seg = w; seg < NSEG; seg += 8) {
        int cnt = g_csc_cnt[g * NSEG + seg];
        const int* lst = g_csc + g * NN + seg * SEGLEN;
        int off = s_off[seg];
        for (int j = 0; j < cnt; j++) {
            int k = lst[j];
            float p = g_xs[k * DD + lane];
            sp += p;
            sl += g_lamx[k * DD + lane];
            se += g_xe[k * DD + lane];
            sm += g_lamm1[k];
            if (cache) {
                s_pT[lane * PT + off + j] = p;          // banks (lane+idx)%32: conflict-free
                if (lane == 0) s_pp[off + j] = g_xsn2[k];
            }
        }
    }
    s_vec[w][0][lane] = sp;
    s_vec[w][1][lane] = sl;
    s_vec[w][2][lane] = se;
    if (lane == 0) s_sc[w] = sm;
    __syncthreads();

    if (w == 0) {
        float tp = 0.f, tl = 0.f, te = 0.f, tm = 0.f;
        #pragma unroll
        for (int u = 0; u < 8; u++) {
            tp += s_vec[u][0][lane];
            tl += s_vec[u][1][lane];
            te += s_vec[u][2][lane];
            tm += s_sc[u];
        }
        g_ee[g * DD + lane] = te / fmaxf(cntf, 1e-6f);

        // gyromidpoint
        float den = fmaxf(tm, 1e-6f);
        float y   = tl / den;
        float yn  = fmaxf(sqrtf(wsum(y * y)), 1e-6f);
        float arg = clip1(sc * yn);
        float eh  = tanhf(0.5f * atanhf(arg)) * y / (sc * yn);
        float sq  = wsum(eh * eh);
        float lam = 2.0f / fmaxf(1.0f - c * sq, 1e-6f);
        g_elamx[g * DD + lane] = lam * eh;
        if (lane == 0) g_elamm1[g] = lam - 1.0f;

        // sphere mu0
        float mu = tp / cntf;
        mu /= fmaxf(sqrtf(wsum(mu * mu)), 1e-6f);
        s_mu[lane] = mu;
        float mm = wsum(mu * mu);
        if (lane == 0) s_mm = mm;
    }
    __syncthreads();

    // ---- phase B: 5 Frechet iterations ----
    for (int it = 0; it < 5; it++) {
        if (cache) {
            // (1) member-per-thread dots: no warp reductions
            float mm = s_mm;
            for (int m = tid; m < tot; m += BK) {
                float d0 = 0.f, d1 = 0.f;
                #pragma unroll
                for (int d = 0; d < DD; d += 2) {
                    d0 = fmaf(s_mu[d],     s_pT[d * PT + m],       d0);
                    d1 = fmaf(s_mu[d + 1], s_pT[(d + 1) * PT + m], d1);
                }
                float draw = d0 + d1;
                float dotc = clip1(draw);
                float theta = acosf(dotc);
                float dn2 = s_pp[m] - dotc * (2.0f * draw - dotc * mm);
                float dn  = fmaxf(sqrtf(fmaxf(dn2, 0.f)), 1e-6f);
                float a   = theta / dn;
                s_a[m]  = a;
                s_ad[m] = a * dotc;
            }
            __syncthreads();
            // (2) dim-per-lane accumulation, warps stripe members
            float tpart = 0.f, bpart = 0.f;
            for (int m = w; m < tot; m += 8) {
                float a = s_a[m];
                tpart = fmaf(a, s_pT[lane * PT + m], tpart);
                bpart += s_ad[m];
            }
            s_tw[w][lane] = tpart;
            if (lane == 0) s_bw[w] = bpart;
        } else {
            // fallback: old per-member warp-reduction path over global lists
            float mu = s_mu[lane];
            float mm = s_mm;
            float t = 0.f, bsum = 0.f;
            for (int seg = w; seg < NSEG; seg += 8) {
                int cnt = g_csc_cnt[g * NSEG + seg];
                const int* lst = g_csc + g * NN + seg * SEGLEN;
                for (int j = 0; j < cnt; j++) {
                    int k = lst[j];
                    float p    = g_xs[k * DD + lane];
                    float draw = wsum(mu * p);
                    float dotc = clip1(draw);
                    float theta = acosf(dotc);
                    float dn2 = g_xsn2[k] - dotc * (2.0f * draw - dotc * mm);
                    float dn  = fmaxf(sqrtf(fmaxf(dn2, 0.f)), 1e-6f);
                    float a   = theta / dn;
                    t    = fmaf(a, p, t);
                    bsum += a * dotc;
                }
            }
            s_tw[w][lane] = t;
            if (lane == 0) s_bw[w] = bsum;
        }
        __syncthreads();
        // (3) warp-0 epilogue: combine partials, exp map, renormalize
        if (w == 0) {
            float mu = s_mu[lane];
            float tsum = 0.f, b = 0.f;
            #pragma unroll
            for (int u = 0; u < 8; u++) { tsum += s_tw[u][lane]; b += s_bw[u]; }
            float t = fmaf(-b, mu, tsum);
            float avg = t / cntf;
            float vn  = sqrtf(wsum(avg * avg));
            float vns = fmaxf(vn, 1e-6f);
            float res = cosf(vn) * mu + sinf(vn) * avg / vns;
            res /= fmaxf(sqrtf(wsum(res * res)), 1e-6f);
            s_mu[lane] = res;
            float mm = wsum(res * res);
            if (lane == 0) s_mm = mm;
        }
        __syncthreads();
    }
    if (w == 0) {
        float mu = s_mu[lane];
        g_es[g * DD + lane] = mu;
        if (lane == 0) g_esn2[g] = s_mm;
    }
}

// ---------------- stage 2: groups -> 2048 nodes (warp per row) ----------------
__global__ void k_agg2(float* __restrict__ out, const float* __restrict__ cph) {
    int i    = blockIdx.x * (blockDim.x >> 5) + (threadIdx.x >> 5);
    int lane = threadIdx.x & 31;
    if (i >= NN) return;

    float c  = fabsf(*cph) + 1e-6f;
    float sc = sqrtf(c);
    float maxn = (1.0f - 1e-5f) / sc;

    int cnt = g_csr_cnt[i];
    const int* lst = g_csr + i * MM;

    float sp = 0.f, sl = 0.f, se = 0.f, sm = 0.f;
    for (int j = 0; j < cnt; j++) {
        int g = lst[j];
        sp += g_es[g * DD + lane];
        sl += g_elamx[g * DD + lane];
        se += g_ee[g * DD + lane];
        sm += g_elamm1[g];
    }
    float cntf = (float)cnt;

    float oe = se / fmaxf(cntf, 1e-6f);

    // gyromidpoint + final hyp_project
    float den = fmaxf(sm, 1e-6f);
    float y   = sl / den;
    float yn  = fmaxf(sqrtf(wsum(y * y)), 1e-6f);
    float arg = clip1(sc * yn);
    float oh  = tanhf(0.5f * atanhf(arg)) * y / (sc * yn);
    float n   = sqrtf(wsum(oh * oh));
    float nm  = fmaxf(n, 1e-6f);
    if (nm > maxn) oh *= maxn / nm;

    // sphere midpoint, 2-way ILP over members
    float mu = sp / cntf;
    mu /= fmaxf(sqrtf(wsum(mu * mu)), 1e-6f);
    for (int it = 0; it < 5; it++) {
        float mm = wsum(mu * mu);
        float t = 0.f, bsum = 0.f;
        int j = 0;
        for (; j + 1 < cnt; j += 2) {
            int g0 = lst[j], g1 = lst[j + 1];
            float p0 = g_es[g0 * DD + lane];
            float p1 = g_es[g1 * DD + lane];
            float w0 = wsum(mu * p0);           // two independent shuffle chains
            float w1 = wsum(mu * p1);
            float dc0 = clip1(w0), dc1 = clip1(w1);
            float th0 = acosf(dc0), th1 = acosf(dc1);
            float q0 = g_esn2[g0] - dc0 * (2.0f * w0 - dc0 * mm);
            float q1 = g_esn2[g1] - dc1 * (2.0f * w1 - dc1 * mm);
            float a0 = th0 / fmaxf(sqrtf(fmaxf(q0, 0.f)), 1e-6f);
            float a1 = th1 / fmaxf(sqrtf(fmaxf(q1, 0.f)), 1e-6f);
            t    = fmaf(a0, p0, t);
            t    = fmaf(a1, p1, t);
            bsum = fmaf(-a0, dc0, bsum);
            bsum = fmaf(-a1, dc1, bsum);
        }
        if (j < cnt) {
            int g0 = lst[j];
            float p0 = g_es[g0 * DD + lane];
            float w0 = wsum(mu * p0);
            float dc0 = clip1(w0);
            float th0 = acosf(dc0);
            float q0 = g_esn2[g0] - dc0 * (2.0f * w0 - dc0 * mm);
            float a0 = th0 / fmaxf(sqrtf(fmaxf(q0, 0.f)), 1e-6f);
            t    = fmaf(a0, p0, t);
            bsum = fmaf(-a0, dc0, bsum);
        }
        t = fmaf(bsum, mu, t);
        t /= cntf;
        float vn  = sqrtf(wsum(t * t));
        float vns = fmaxf(vn, 1e-6f);
        mu = cosf(vn) * mu + sinf(vn) * t / vns;
        mu /= fmaxf(sqrtf(wsum(mu * mu)), 1e-6f);
    }
    float os = mu / fmaxf(sqrtf(wsum(mu * mu)), 1e-6f);

    out[i * 96 + lane]      = oh;
    out[i * 96 + 32 + lane] = os;
    out[i * 96 + 64 + lane] = oe;
}

// ---------------- launch ----------------
extern "C" void kernel_launch(void* const* d_in, const int* in_sizes, int n_in,
                              void* d_out, int out_size) {
    const float* x   = (const float*)d_in[0];
    const float* H   = (const float*)d_in[1];
    const float* Wh  = (const float*)d_in[2];
    const float* bh  = (const float*)d_in[3];
    const float* Ws  = (const float*)d_in[4];
    const float* bs  = (const float*)d_in[5];
    const float* We  = (const float*)d_in[6];
    const float* be  = (const float*)d_in[7];
    const float* c_h = (const float*)d_in[8];
    float* out = (float*)d_out;

    k_build_csr<<<NN / 8, 256>>>(H);
    k_build_csc<<<NSEG, MM>>>(H);
    k_transform<<<NN / 4, 128>>>(x, Wh, bh, Ws, bs, We, be, c_h);
    k_agg1<<<MM, BK>>>(c_h);
    k_agg2<<<NN / 4, 128>>>(out, c_h);
}

// round 4
// speedup vs baseline: 2.8878x; 1.7455x over previous
#include <cuda_runtime.h>
#include <math.h>

#define NN 2048          // nodes
#define MM 512           // groups
#define DD 32            // per-manifold dim
#define NSEG 32          // k-segments for CSC build
#define SEGLEN 64        // NN / NSEG
#define CAP 256          // member cache capacity in k_agg1
#define PT 257           // padded stride for agg1 transposed cache
#define CAP2 48          // member cache capacity per row in k_agg2
#define ST2 49           // padded stride for agg2 transposed cache
#define BK 256           // k_agg1 block size (8 warps)
#define FULL 0xffffffffu

// grid-role split for fused pre kernel
#define CSR_BLOCKS 256   // 8 rows/block (warp per row)
#define CSC_BLOCKS 64    // 32 segs x 2 column-halves
#define TRF_BLOCKS 256   // 8 rows/block
#define PRE_BLOCKS (CSR_BLOCKS + CSC_BLOCKS + TRF_BLOCKS)

// ---------------- device scratch (no allocs allowed) ----------------
__device__ float g_xs[NN*DD], g_xe[NN*DD];
__device__ float g_lamx[NN*DD];
__device__ float g_lamm1[NN];
__device__ float g_xsn2[NN];

__device__ int   g_csr[NN*MM];
__device__ int   g_csr_cnt[NN];
__device__ int   g_csc[MM*NN];
__device__ int   g_csc_cnt[MM*NSEG];

__device__ float g_es[MM*DD], g_ee[MM*DD];
__device__ float g_elamx[MM*DD];
__device__ float g_elamm1[MM];
__device__ float g_esn2[MM];

// ---------------- helpers ----------------
__device__ __forceinline__ float wsum(float v) {
    #pragma unroll
    for (int o = 16; o; o >>= 1) v += __shfl_xor_sync(FULL, v, o);
    return v;
}
__device__ __forceinline__ float clip1(float v) {
    return fminf(fmaxf(v, -1.0f + 1e-6f), 1.0f - 1e-6f);
}

// ---------------- fused pre kernel: csr | csc | transform by block range ----
__global__ __launch_bounds__(256) void k_pre(const float* __restrict__ x,
                          const float* __restrict__ H,
                          const float* __restrict__ Wh, const float* __restrict__ bh,
                          const float* __restrict__ Ws, const float* __restrict__ bs,
                          const float* __restrict__ We, const float* __restrict__ be,
                          const float* __restrict__ cph) {
    int b = blockIdx.x;
    if (b < CSR_BLOCKS) {
        // ---- CSR: warp per row ----
        int warp = b * 8 + (threadIdx.x >> 5);
        int lane = threadIdx.x & 31;
        const float* row = H + (size_t)warp * MM;
        int cnt = 0;
        for (int gb = 0; gb < MM; gb += 32) {
            float h = row[gb + lane];
            unsigned mask = __ballot_sync(FULL, h > 0.5f);
            if (lane == 0) {
                while (mask) {
                    int bi = __ffs(mask) - 1;
                    g_csr[warp * MM + cnt++] = gb + bi;
                    mask &= mask - 1;
                }
            }
        }
        if (lane == 0) g_csr_cnt[warp] = cnt;
        return;
    }
    if (b < CSR_BLOCKS + CSC_BLOCKS) {
        // ---- CSC: thread = column, 2 blocks per segment ----
        int rel  = b - CSR_BLOCKS;
        int seg  = rel >> 1;
        int g    = ((rel & 1) << 8) + threadIdx.x;      // 0..511
        int cnt  = 0;
        int base = g * NN + seg * SEGLEN;
        int k0   = seg * SEGLEN;
        for (int j = 0; j < SEGLEN; j++) {
            float h = H[(size_t)(k0 + j) * MM + g];     // coalesced across g
            if (h > 0.5f) g_csc[base + cnt++] = k0 + j;
        }
        g_csc_cnt[g * NSEG + seg] = cnt;
        return;
    }
    // ---- transform: warp per row, 8 rows/block ----
    __shared__ float sW[3 * DD * DD];
    __shared__ float sB[3 * DD];
    for (int i = threadIdx.x; i < DD * DD; i += blockDim.x) {
        sW[i]             = Wh[i];
        sW[DD*DD + i]     = Ws[i];
        sW[2*DD*DD + i]   = We[i];
    }
    if (threadIdx.x < DD) {
        sB[threadIdx.x]        = bh[threadIdx.x];
        sB[DD + threadIdx.x]   = bs[threadIdx.x];
        sB[2*DD + threadIdx.x] = be[threadIdx.x];
    }
    __syncthreads();

    int r    = (b - CSR_BLOCKS - CSC_BLOCKS) * 8 + (threadIdx.x >> 5);
    int lane = threadIdx.x & 31;

    float c  = fabsf(*cph) + 1e-6f;
    float sc = sqrtf(c);
    float maxn = (1.0f - 1e-5f) / sc;

    float xh = x[r * 96 + lane];
    float xs = x[r * 96 + 32 + lane];
    float xe = x[r * 96 + 64 + lane];

    // hyp_project(x_h)
    float n  = sqrtf(wsum(xh * xh));
    float nm = fmaxf(n, 1e-6f);
    if (nm > maxn) xh *= maxn / nm;

    // logmap0
    n = fmaxf(sqrtf(wsum(xh * xh)), 1e-6f);
    float arg = clip1(sc * n);
    float lg  = atanhf(arg) * xh / (sc * n);

    // v = lg @ Wh^T + bh
    float v = sB[lane];
    #pragma unroll
    for (int i = 0; i < DD; i++)
        v = fmaf(__shfl_sync(FULL, lg, i), sW[lane * DD + i], v);

    // expmap0
    n = fmaxf(sqrtf(wsum(v * v)), 1e-6f);
    float xh2 = tanhf(sc * n) * v / (sc * n);
    // hyp_project
    n  = sqrtf(wsum(xh2 * xh2));
    nm = fmaxf(n, 1e-6f);
    if (nm > maxn) xh2 *= maxn / nm;

    float sq  = wsum(xh2 * xh2);
    float lam = 2.0f / fmaxf(1.0f - c * sq, 1e-6f);
    g_lamx[r * DD + lane] = lam * xh2;
    if (lane == 0) g_lamm1[r] = lam - 1.0f;

    // sphere branch
    n = fmaxf(sqrtf(wsum(xs * xs)), 1e-6f);
    xs /= n;
    float s2 = sB[DD + lane];
    #pragma unroll
    for (int i = 0; i < DD; i++)
        s2 = fmaf(__shfl_sync(FULL, xs, i), sW[DD*DD + lane * DD + i], s2);
    n = fmaxf(sqrtf(wsum(s2 * s2)), 1e-6f);
    s2 /= n;
    g_xs[r * DD + lane] = s2;
    float pn = wsum(s2 * s2);
    if (lane == 0) g_xsn2[r] = pn;

    // euclidean branch
    float e2 = sB[2*DD + lane];
    #pragma unroll
    for (int i = 0; i < DD; i++)
        e2 = fmaf(__shfl_sync(FULL, xe, i), sW[2*DD*DD + lane * DD + i], e2);
    g_xe[r * DD + lane] = e2;
}

// ---------------- stage 1: nodes -> 512 groups (block per group) ----------------
__global__ __launch_bounds__(BK) void k_agg1(const float* __restrict__ cph) {
    __shared__ float s_pT[DD * PT];     // transposed points [d][m]
    __shared__ float s_pp[CAP];
    __shared__ float s_a[CAP];
    __shared__ float s_ad[CAP];         // a * dotc
    __shared__ float s_ar[CAP];         // a * draw
    __shared__ float s_mu[DD];
    __shared__ float s_vec[8][3][DD];
    __shared__ float s_sc[8];
    __shared__ float s_tw[8][DD];
    __shared__ float s_bw[8];
    __shared__ float s_brw[8];
    __shared__ int   s_off[NSEG];
    __shared__ int   s_tot;

    int g    = blockIdx.x;
    int w    = threadIdx.x >> 5;
    int lane = threadIdx.x & 31;
    int tid  = threadIdx.x;

    float c  = fabsf(*cph) + 1e-6f;
    float sc = sqrtf(c);

    if (tid == 0) {
        int acc = 0;
        for (int s = 0; s < NSEG; s++) { s_off[s] = acc; acc += g_csc_cnt[g * NSEG + s]; }
        s_tot = acc;
    }
    __syncthreads();
    int tot = s_tot;
    bool cache = (tot <= CAP);
    float cntf = (float)tot;

    // ---- phase A: linear sums + transposed SMEM member cache ----
    float sp = 0.f, sl = 0.f, se = 0.f, sm = 0.f;
    for (int seg = w; seg < NSEG; seg += 8) {
        int cnt = g_csc_cnt[g * NSEG + seg];
        const int* lst = g_csc + g * NN + seg * SEGLEN;
        int off = s_off[seg];
        for (int j = 0; j < cnt; j++) {
            int k = lst[j];
            float p = g_xs[k * DD + lane];
            sp += p;
            sl += g_lamx[k * DD + lane];
            se += g_xe[k * DD + lane];
            sm += g_lamm1[k];
            if (cache) {
                s_pT[lane * PT + off + j] = p;
                if (lane == 0) s_pp[off + j] = g_xsn2[k];
            }
        }
    }
    s_vec[w][0][lane] = sp;
    s_vec[w][1][lane] = sl;
    s_vec[w][2][lane] = se;
    if (lane == 0) s_sc[w] = sm;
    __syncthreads();

    if (w == 0) {
        float tp = 0.f, tl = 0.f, te = 0.f, tm = 0.f;
        #pragma unroll
        for (int u = 0; u < 8; u++) {
            tp += s_vec[u][0][lane];
            tl += s_vec[u][1][lane];
            te += s_vec[u][2][lane];
            tm += s_sc[u];
        }
        g_ee[g * DD + lane] = te / fmaxf(cntf, 1e-6f);

        // gyromidpoint
        float den = fmaxf(tm, 1e-6f);
        float y   = tl / den;
        float yn  = fmaxf(sqrtf(wsum(y * y)), 1e-6f);
        float arg = clip1(sc * yn);
        float eh  = tanhf(0.5f * atanhf(arg)) * y / (sc * yn);
        float sq  = wsum(eh * eh);
        float lam = 2.0f / fmaxf(1.0f - c * sq, 1e-6f);
        g_elamx[g * DD + lane] = lam * eh;
        if (lane == 0) g_elamm1[g] = lam - 1.0f;

        // sphere mu0 (unit norm => mm == 1 henceforth)
        float mu = tp / cntf;
        mu /= fmaxf(sqrtf(wsum(mu * mu)), 1e-6f);
        s_mu[lane] = mu;
    }
    __syncthreads();

    // ---- phase B: 5 Frechet iterations ----
    for (int it = 0; it < 5; it++) {
        if (cache) {
            // (1) member-per-thread dots
            for (int m = tid; m < tot; m += BK) {
                float d0 = 0.f, d1 = 0.f;
                #pragma unroll
                for (int d = 0; d < DD; d += 2) {
                    d0 = fmaf(s_mu[d],     s_pT[d * PT + m],       d0);
                    d1 = fmaf(s_mu[d + 1], s_pT[(d + 1) * PT + m], d1);
                }
                float draw = d0 + d1;
                float dotc = clip1(draw);
                float theta = acosf(dotc);
                float dn2 = s_pp[m] - dotc * (2.0f * draw - dotc);   // mm = 1
                float dn  = fmaxf(sqrtf(fmaxf(dn2, 0.f)), 1e-6f);
                float a   = theta / dn;
                s_a[m]  = a;
                s_ad[m] = a * dotc;
                s_ar[m] = a * draw;
            }
            __syncthreads();
            // (2) dim-per-lane accumulation, warps stripe members
            float tpart = 0.f, bpart = 0.f, brpart = 0.f;
            for (int m = w; m < tot; m += 8) {
                tpart  = fmaf(s_a[m], s_pT[lane * PT + m], tpart);
                bpart  += s_ad[m];
                brpart += s_ar[m];
            }
            s_tw[w][lane] = tpart;
            if (lane == 0) { s_bw[w] = bpart; s_brw[w] = brpart; }
        } else {
            float mu = s_mu[lane];
            float t = 0.f, bsum = 0.f, brsum = 0.f;
            for (int seg = w; seg < NSEG; seg += 8) {
                int cnt = g_csc_cnt[g * NSEG + seg];
                const int* lst = g_csc + g * NN + seg * SEGLEN;
                for (int j = 0; j < cnt; j++) {
                    int k = lst[j];
                    float p    = g_xs[k * DD + lane];
                    float draw = wsum(mu * p);
                    float dotc = clip1(draw);
                    float theta = acosf(dotc);
                    float dn2 = g_xsn2[k] - dotc * (2.0f * draw - dotc);
                    float dn  = fmaxf(sqrtf(fmaxf(dn2, 0.f)), 1e-6f);
                    float a   = theta / dn;
                    t     = fmaf(a, p, t);
                    bsum  += a * dotc;
                    brsum += a * draw;
                }
            }
            s_tw[w][lane] = t;
            if (lane == 0) { s_bw[w] = bsum; s_brw[w] = brsum; }
        }
        __syncthreads();
        // (3) epilogue: ALL warps compute identical result (no 3rd barrier)
        {
            float mu = s_mu[lane];
            float tsum = 0.f, bt = 0.f, br = 0.f;
            #pragma unroll
            for (int u = 0; u < 8; u++) { tsum += s_tw[u][lane]; bt += s_bw[u]; br += s_brw[u]; }
            float t = fmaf(-bt, mu, tsum);
            float avg = t / cntf;
            float vn2 = wsum(avg * avg);                 // only reduction in epilogue
            float vn  = sqrtf(vn2);
            float vns = fmaxf(vn, 1e-6f);
            float cv = cosf(vn), sv = sinf(vn);
            float mudotavg = (br - bt) / cntf;           // mu . avg  (mm = 1)
            float r   = cv * mu + sv * avg / vns;
            float svv = sv / vns;
            float rn2 = fmaf(cv * cv, 1.0f, fmaf(2.0f * cv * svv, mudotavg, svv * svv * vn2));
            float rn  = fmaxf(sqrtf(rn2), 1e-6f);
            s_mu[lane] = r / rn;                         // all warps write same value
        }
        __syncthreads();
    }
    if (w == 0) {
        float mu = s_mu[lane];
        g_es[g * DD + lane] = mu;
        float pn = wsum(mu * mu);
        if (lane == 0) g_esn2[g] = pn;
    }
}

// ---------------- stage 2: groups -> 2048 nodes (warp per row, SMEM cache) ------
__global__ __launch_bounds__(128) void k_agg2(float* __restrict__ out, const float* __restrict__ cph) {
    __shared__ float s_pT[4][DD * ST2];   // per-warp transposed member cache
    __shared__ float s_pp[4][CAP2];
    __shared__ float s_a[4][CAP2];
    __shared__ float s_mu[4][DD];

    int w    = threadIdx.x >> 5;
    int lane = threadIdx.x & 31;
    int i    = blockIdx.x * 4 + w;

    float c  = fabsf(*cph) + 1e-6f;
    float sc = sqrtf(c);
    float maxn = (1.0f - 1e-5f) / sc;

    int cnt = g_csr_cnt[i];
    const int* lst = g_csr + i * MM;
    bool cache = (cnt <= CAP2);
    float cntf = (float)cnt;

    // prologue: linear sums + cache
    float sp = 0.f, sl = 0.f, se = 0.f, sm = 0.f;
    for (int j = 0; j < cnt; j++) {
        int g = lst[j];
        float p = g_es[g * DD + lane];
        sp += p;
        sl += g_elamx[g * DD + lane];
        se += g_ee[g * DD + lane];
        sm += g_elamm1[g];
        if (cache) {
            s_pT[w][lane * ST2 + j] = p;
            if (lane == 0) s_pp[w][j] = g_esn2[g];
        }
    }

    float oe = se / fmaxf(cntf, 1e-6f);

    // gyromidpoint + final hyp_project
    float den = fmaxf(sm, 1e-6f);
    float y   = sl / den;
    float yn  = fmaxf(sqrtf(wsum(y * y)), 1e-6f);
    float arg = clip1(sc * yn);
    float oh  = tanhf(0.5f * atanhf(arg)) * y / (sc * yn);
    float n   = sqrtf(wsum(oh * oh));
    float nm  = fmaxf(n, 1e-6f);
    if (nm > maxn) oh *= maxn / nm;

    // sphere midpoint
    float mu = sp / cntf;
    mu /= fmaxf(sqrtf(wsum(mu * mu)), 1e-6f);

    if (cache) {
        s_mu[w][lane] = mu;
        __syncwarp();
        for (int it = 0; it < 5; it++) {
            // (1) lane = member: dots, no shuffles
            float asum_d = 0.f, asum_r = 0.f;
            for (int m = lane; m < cnt; m += 32) {
                float d0 = 0.f, d1 = 0.f;
                #pragma unroll
                for (int d = 0; d < DD; d += 2) {
                    d0 = fmaf(s_mu[w][d],     s_pT[w][d * ST2 + m],       d0);
                    d1 = fmaf(s_mu[w][d + 1], s_pT[w][(d + 1) * ST2 + m], d1);
                }
                float draw = d0 + d1;
                float dotc = clip1(draw);
                float theta = acosf(dotc);
                float dn2 = s_pp[w][m] - dotc * (2.0f * draw - dotc);  // mm = 1
                float dn  = fmaxf(sqrtf(fmaxf(dn2, 0.f)), 1e-6f);
                float a   = theta / dn;
                s_a[w][m] = a;
                asum_d = fmaf(a, dotc, asum_d);
                asum_r = fmaf(a, draw, asum_r);
            }
            __syncwarp();
            float bt = wsum(asum_d);
            float br = wsum(asum_r);
            // (2) lane = dim accumulation
            float t0 = 0.f, t1 = 0.f;
            int m = 0;
            for (; m + 1 < cnt; m += 2) {
                t0 = fmaf(s_a[w][m],     s_pT[w][lane * ST2 + m],     t0);
                t1 = fmaf(s_a[w][m + 1], s_pT[w][lane * ST2 + m + 1], t1);
            }
            if (m < cnt) t0 = fmaf(s_a[w][m], s_pT[w][lane * ST2 + m], t0);
            float mul = s_mu[w][lane];
            float t = fmaf(-bt, mul, t0 + t1);
            float avg = t / cntf;
            float vn2 = wsum(avg * avg);
            float vn  = sqrtf(vn2);
            float vns = fmaxf(vn, 1e-6f);
            float cv = cosf(vn), sv = sinf(vn);
            float mudotavg = (br - bt) / cntf;
            float r   = cv * mul + sv * avg / vns;
            float svv = sv / vns;
            float rn2 = fmaf(cv * cv, 1.0f, fmaf(2.0f * cv * svv, mudotavg, svv * svv * vn2));
            float rn  = fmaxf(sqrtf(rn2), 1e-6f);
            mul = r / rn;
            s_mu[w][lane] = mul;
            __syncwarp();
        }
        mu = s_mu[w][lane];
    } else {
        // fallback: shuffle-based path over global lists (rare)
        for (int it = 0; it < 5; it++) {
            float mm = wsum(mu * mu);
            float t = 0.f, bsum = 0.f;
            for (int j = 0; j < cnt; j++) {
                int g0 = lst[j];
                float p0 = g_es[g0 * DD + lane];
                float w0 = wsum(mu * p0);
                float dc0 = clip1(w0);
                float th0 = acosf(dc0);
                float q0 = g_esn2[g0] - dc0 * (2.0f * w0 - dc0 * mm);
                float a0 = th0 / fmaxf(sqrtf(fmaxf(q0, 0.f)), 1e-6f);
                t    = fmaf(a0, p0, t);
                bsum = fmaf(-a0, dc0, bsum);
            }
            t = fmaf(bsum, mu, t);
            t /= cntf;
            float vn  = sqrtf(wsum(t * t));
            float vns = fmaxf(vn, 1e-6f);
            mu = cosf(vn) * mu + sinf(vn) * t / vns;
            mu /= fmaxf(sqrtf(wsum(mu * mu)), 1e-6f);
        }
    }
    float os = mu / fmaxf(sqrtf(wsum(mu * mu)), 1e-6f);

    out[i * 96 + lane]      = oh;
    out[i * 96 + 32 + lane] = os;
    out[i * 96 + 64 + lane] = oe;
}

// ---------------- launch ----------------
extern "C" void kernel_launch(void* const* d_in, const int* in_sizes, int n_in,
                              void* d_out, int out_size) {
    const float* x   = (const float*)d_in[0];
    const float* H   = (const float*)d_in[1];
    const float* Wh  = (const float*)d_in[2];
    const float* bh  = (const float*)d_in[3];
    const float* Ws  = (const float*)d_in[4];
    const float* bs  = (const float*)d_in[5];
    const float* We  = (const float*)d_in[6];
    const float* be  = (const float*)d_in[7];
    const float* c_h = (const float*)d_in[8];
    float* out = (float*)d_out;

    k_pre<<<PRE_BLOCKS, 256>>>(x, H, Wh, bh, Ws, bs, We, be, c_h);
    k_agg1<<<MM, BK>>>(c_h);
    k_agg2<<<NN / 4, 128>>>(out, c_h);
}